// round 13
// baseline (speedup 1.0000x reference)
#include <cuda_runtime.h>
#include <cuda_fp16.h>
#include <math.h>
#include <stdint.h>

typedef unsigned int u32;
typedef unsigned long long u64;

// ---------------------------------------------------------------------------
// vgae_decoder, warp-specialized single-pass fp16 mma, 3 CTAs/SM:
//   D = fp16(xu)*fp16(xv) relu'd @ fp16(W1)   (fp32 accumulate)
// R13: 256-thread CTAs, __launch_bounds__(256,3) -> 24 warps/SM (occ 37.5%).
//      Consumer accumulators chunked over n (2 x 32 cols, acc=32 regs) so the
//      whole kernel fits 85 regs/thread. TILE_E 64, NBUF=2 ring, named
//      barriers (128 producer / 128 consumer threads).
// ---------------------------------------------------------------------------

#define A_PITCH 272
#define SM_B   0
#define SM_A   32768
#define A_BUF  17408                     // 64 rows * 272
#define NBUF   2
#define SM_MISC (SM_A + NBUF * A_BUF)    // 67584
#define SMEM_TOTAL (SM_MISC + 2048)      // 69632 (x3 = 208896 <= SM smem)
#define NTHREADS 256
#define TILE_E 64
#define MAX_NODES 100000

__device__ u64 g_Bh[4096];               // fp16 W1 fragments, mma order
__device__ u64 g_xh[MAX_NODES * 32];     // fp16 x, 32 u64 per row

#define NB_ARRIVE(id) asm volatile("bar.arrive %0, 256;" :: "r"(id) : "memory")
#define NB_SYNC(id)   asm volatile("bar.sync %0, 256;"   :: "r"(id) : "memory")

__device__ __forceinline__ u32 pack_hf2(__half a, __half b) {
    __half2 t; t.x = a; t.y = b; return *(u32*)&t;
}
__device__ __forceinline__ u32 smem_u32(const void* p) {
    u32 a; asm("{ .reg .u64 t; cvta.to.shared.u64 t, %1; cvt.u32.u64 %0, t; }"
               : "=r"(a) : "l"(p)); return a;
}
__device__ __forceinline__ void ldmatrix_x4(u32* r, u32 saddr) {
    asm volatile("ldmatrix.sync.aligned.m8n8.x4.shared.b16 {%0,%1,%2,%3}, [%4];"
                 : "=r"(r[0]), "=r"(r[1]), "=r"(r[2]), "=r"(r[3]) : "r"(saddr));
}
__device__ __forceinline__ void mma_fp16(float* d, const u32* a, const u32* b) {
    asm volatile(
        "mma.sync.aligned.m16n8k16.row.col.f32.f16.f16.f32 "
        "{%0,%1,%2,%3}, {%4,%5,%6,%7}, {%8,%9}, {%0,%1,%2,%3};"
        : "+f"(d[0]), "+f"(d[1]), "+f"(d[2]), "+f"(d[3])
        : "r"(a[0]), "r"(a[1]), "r"(a[2]), "r"(a[3]), "r"(b[0]), "r"(b[1]));
}

// ---- prep: W1 -> fp16 fragments ----
__global__ void prep_kernel(const float* __restrict__ W1) {
    int t = blockIdx.x * blockDim.x + threadIdx.x;
    if (t >= 4096) return;
    int lane = t & 31, nt = (t >> 5) & 15, kt = t >> 9;
    int n  = nt * 8 + (lane >> 2);
    int k0 = kt * 16 + (lane & 3) * 2;
    __half h0 = __float2half(W1[(k0    ) * 128 + n]);
    __half h1 = __float2half(W1[(k0 + 1) * 128 + n]);
    __half h2 = __float2half(W1[(k0 + 8) * 128 + n]);
    __half h3 = __float2half(W1[(k0 + 9) * 128 + n]);
    int idx = ((kt * 8 + (nt >> 1)) * 32 + lane) * 2 + (nt & 1);
    g_Bh[idx] = ((u64)pack_hf2(h2, h3) << 32) | pack_hf2(h0, h1);
}

// ---- prep: x -> fp16 ----
__global__ void prep_x_kernel(const float* __restrict__ x, int n4) {
    int i = blockIdx.x * blockDim.x + threadIdx.x;
    if (i >= n4) return;
    float4 v = ((const float4*)x)[i];
    u64 p;
    ((__half2*)&p)[0] = __floats2half2_rn(v.x, v.y);
    ((__half2*)&p)[1] = __floats2half2_rn(v.z, v.w);
    g_xh[i] = p;
}

__device__ __forceinline__ void conv_store(char* smem, u32 base, int row,
                                           int lane, u64 ua, u64 ub,
                                           bool valid) {
    u64 hp = 0;
    if (valid) {
        __half2 z = __float2half2_rn(0.f);
        ((__half2*)&hp)[0] =
            __hmax2(__hmul2(((__half2*)&ua)[0], ((__half2*)&ub)[0]), z);
        ((__half2*)&hp)[1] =
            __hmax2(__hmul2(((__half2*)&ua)[1], ((__half2*)&ub)[1]), z);
    }
    u32 off = (u32)row * A_PITCH + (u32)lane * 8;
    *(u64*)(smem + base + off) = hp;
}

__global__ void __launch_bounds__(NTHREADS, 3)
vgae_mma_kernel(const float* __restrict__ b1g,
                const float* __restrict__ W2,
                const float* __restrict__ b2g,
                const int*   __restrict__ ei_pos,
                const int*   __restrict__ ei_neg,
                float*       __restrict__ out,
                int E, int total, int n_tiles)
{
    extern __shared__ char smem[];
    float* sB1  = (float*)(smem + SM_MISC);          // 128 f32
    float* sW2  = (float*)(smem + SM_MISC + 512);    // 128 f32
    float* sRed = (float*)(smem + SM_MISC + 1024);   // [2][64][2] f32

    const int tid  = threadIdx.x;
    const int wid  = tid >> 5;
    const int lane = tid & 31;
    const u32 sbase = smem_u32(smem);

    {
        u64* bh = (u64*)(smem + SM_B);
        #pragma unroll 4
        for (int i = tid; i < 4096; i += NTHREADS) bh[i] = g_Bh[i];
        if (tid < 128) { sB1[tid] = b1g[tid]; sW2[tid] = W2[tid]; }
    }
    const float b2v = __ldg(b2g);
    __syncthreads();

    const bool is_prod = (wid < 4);
    const int r0 = (wid & 3) * 16;   // producer rows r0..r0+15
    const int nit = (n_tiles > (int)blockIdx.x)
                  ? (n_tiles - blockIdx.x + gridDim.x - 1) / gridDim.x : 0;

    #define LOAD_IDX(T, IDXV) do {                                           \
        (IDXV) = 0;                                                          \
        int _e0 = (T) * TILE_E + r0;                                         \
        const int* _ei = ei_pos; int _el = _e0;                              \
        if (_el >= E) { _ei = ei_neg; _el -= E; }                            \
        if (_e0 + (lane & 15) < total)                                       \
            (IDXV) = __ldg(_ei + _el + (lane & 15) + ((lane >= 16) ? E : 0));\
    } while (0)

    #define FETCH_ROW(IDXV, J, UA, UB, VAL, TBASE) do {                      \
        (VAL) = ((TBASE) + r0 + (J)) < total;                                \
        int _u = __shfl_sync(0xffffffffu, (IDXV), (J));                      \
        int _v = __shfl_sync(0xffffffffu, (IDXV), (J) + 16);                 \
        (UA) = __ldg(g_xh + (size_t)_u * 32 + lane);                         \
        (UB) = __ldg(g_xh + (size_t)_v * 32 + lane);                         \
    } while (0)

    #define GATHER16(IDXV, BASE, TBASE) do {                                 \
        _Pragma("unroll")                                                    \
        for (int w = 0; w < 2; ++w) {                                        \
            u64 xa[8], xb[8]; bool vv[8];                                    \
            _Pragma("unroll")                                                \
            for (int j = 0; j < 8; ++j)                                      \
                FETCH_ROW(IDXV, w * 8 + j, xa[j], xb[j], vv[j], TBASE);      \
            _Pragma("unroll")                                                \
            for (int j = 0; j < 8; ++j)                                      \
                conv_store(smem, BASE, r0 + w * 8 + j, lane, xa[j], xb[j],   \
                           vv[j]);                                           \
        }                                                                    \
    } while (0)

    if (is_prod) {
        // ==================== PRODUCER WARPS (0-3) ====================
        int i = 0;
        for (int tile = blockIdx.x; tile < n_tiles; tile += gridDim.x, ++i) {
            int b = i & 1;
            if (i >= NBUF) {
                NB_SYNC(3 + b);                    // buffer b free + sRed ready
                if (tid < TILE_E) {
                    int e = (tile - NBUF * (int)gridDim.x) * TILE_E + tid;
                    if (e < total) {
                        const float* rp = sRed + b * 128 + tid * 2;
                        float s = rp[0] + rp[1] + b2v;
                        out[e] = 1.f / (1.f + expf(-s));
                    }
                }
            }
            int idxv; LOAD_IDX(tile, idxv);
            GATHER16(idxv, SM_A + (u32)b * A_BUF, tile * TILE_E);
            NB_ARRIVE(1 + b);                      // buffer b full
        }
        int j0 = (nit >= NBUF) ? nit - NBUF : 0;
        for (int j = j0; j < nit; ++j) {
            int b = j & 1;
            NB_SYNC(3 + b);
            if (tid < TILE_E) {
                int e = ((int)blockIdx.x + j * (int)gridDim.x) * TILE_E + tid;
                if (e < total) {
                    const float* rp = sRed + b * 128 + tid * 2;
                    float s = rp[0] + rp[1] + b2v;
                    out[e] = 1.f / (1.f + expf(-s));
                }
            }
        }
    } else {
        // ==================== CONSUMER WARPS (4-7) ====================
        const int cw = wid - 4;
        const int wm = cw & 1;           // 32-row m-strip
        const int wn = cw >> 1;          // 64-col n-strip
        const u32 a_lm0 = (u32)(wm * 32 + (lane & 15)) * A_PITCH
                        + (u32)(lane >> 4) * 16;

        int i = 0;
        for (int tile = blockIdx.x; tile < n_tiles; tile += gridDim.x, ++i) {
            int b = i & 1;
            NB_SYNC(1 + b);                        // buffer b full

            const u32 a_lm = sbase + SM_A + (u32)b * A_BUF + a_lm0;
            float p[2][2] = {{0.f, 0.f}, {0.f, 0.f}};   // [mf][row-half]

            #pragma unroll
            for (int c = 0; c < 2; ++c) {          // 32-col chunk
                float acc[2][4][4];
                #pragma unroll
                for (int mf = 0; mf < 2; ++mf)
                    #pragma unroll
                    for (int nt = 0; nt < 4; ++nt)
                        #pragma unroll
                        for (int q = 0; q < 4; ++q) acc[mf][nt][q] = 0.f;

                #pragma unroll
                for (int kt = 0; kt < 8; ++kt) {
                    u32 ah[2][4];
                    #pragma unroll
                    for (int mf = 0; mf < 2; ++mf)
                        ldmatrix_x4(ah[mf], a_lm + (u32)mf * (16 * A_PITCH)
                                            + (u32)kt * 32);
                    u32 bq[4][2];
                    #pragma unroll
                    for (int np = 0; np < 2; ++np) {
                        u32 boff = (u32)(((kt * 8 + wn * 4 + c * 2 + np) * 32
                                          + lane) * 16);
                        uint4 q = *(const uint4*)(smem + SM_B + boff);
                        bq[np*2][0] = q.x; bq[np*2][1] = q.y;
                        bq[np*2+1][0] = q.z; bq[np*2+1][1] = q.w;
                    }
                    #pragma unroll
                    for (int mf = 0; mf < 2; ++mf)
                        #pragma unroll
                        for (int nt = 0; nt < 4; ++nt)
                            mma_fp16(acc[mf][nt], ah[mf], bq[nt]);
                }
                // fold chunk into per-row partials
                #pragma unroll
                for (int mf = 0; mf < 2; ++mf)
                    #pragma unroll
                    for (int nt = 0; nt < 4; ++nt) {
                        int n = wn * 64 + c * 32 + nt * 8 + (lane & 3) * 2;
                        float bia0 = sB1[n], bia1 = sB1[n + 1];
                        float w20  = sW2[n], w21  = sW2[n + 1];
                        p[mf][0] = fmaf(fmaxf(acc[mf][nt][0] + bia0, 0.f), w20,
                                        p[mf][0]);
                        p[mf][0] = fmaf(fmaxf(acc[mf][nt][1] + bia1, 0.f), w21,
                                        p[mf][0]);
                        p[mf][1] = fmaf(fmaxf(acc[mf][nt][2] + bia0, 0.f), w20,
                                        p[mf][1]);
                        p[mf][1] = fmaf(fmaxf(acc[mf][nt][3] + bia1, 0.f), w21,
                                        p[mf][1]);
                    }
            }

            #pragma unroll
            for (int mf = 0; mf < 2; ++mf) {
                float p0 = p[mf][0], p1 = p[mf][1];
                p0 += __shfl_xor_sync(0xffffffffu, p0, 1);
                p0 += __shfl_xor_sync(0xffffffffu, p0, 2);
                p1 += __shfl_xor_sync(0xffffffffu, p1, 1);
                p1 += __shfl_xor_sync(0xffffffffu, p1, 2);
                if ((lane & 3) == 0) {
                    int rr = wm * 32 + mf * 16 + (lane >> 2);
                    float* rb = sRed + b * 128;
                    rb[rr * 2 + wn] = p0;
                    rb[(rr + 8) * 2 + wn] = p1;
                }
            }
            NB_ARRIVE(3 + b);                      // buffer b free + sRed ready
        }
    }
    #undef LOAD_IDX
    #undef FETCH_ROW
    #undef GATHER16
}

// ---------------------------------------------------------------------------
extern "C" void kernel_launch(void* const* d_in, const int* in_sizes, int n_in,
                              void* d_out, int out_size)
{
    const float* x  = (const float*)d_in[0];
    const float* W1 = (const float*)d_in[1];
    const float* b1 = (const float*)d_in[2];
    const float* W2 = (const float*)d_in[3];
    const float* b2 = (const float*)d_in[4];
    const int* eip  = (const int*)d_in[5];
    const int* ein  = (const int*)d_in[6];
    float* out = (float*)d_out;

    int E       = in_sizes[5] / 2;
    int total   = out_size;
    int n_tiles = (total + TILE_E - 1) / TILE_E;

    int n4 = in_sizes[0] / 4;
    if (n4 > MAX_NODES * 32) n4 = MAX_NODES * 32;

    prep_kernel<<<16, 256>>>(W1);
    prep_x_kernel<<<(n4 + 255) / 256, 256>>>(x, n4);

    cudaFuncSetAttribute(vgae_mma_kernel,
                         cudaFuncAttributeMaxDynamicSharedMemorySize, SMEM_TOTAL);
    int grid = 148 * 3;
    if (grid > n_tiles) grid = n_tiles;
    vgae_mma_kernel<<<grid, NTHREADS, SMEM_TOTAL>>>(b1, W2, b2, eip, ein,
                                                    out, E, total, n_tiles);
}

// round 14
// speedup vs baseline: 1.5499x; 1.5499x over previous
#include <cuda_runtime.h>
#include <cuda_fp16.h>
#include <math.h>
#include <stdint.h>

typedef unsigned int u32;
typedef unsigned long long u64;

// ---------------------------------------------------------------------------
// vgae_decoder, warp-specialized single-pass fp16 mma:
//   D = fp16(xu)*fp16(xv) relu'd @ fp16(W1)   (fp32 accumulate)
// R14: 640 threads = 4 producer warps + 16 consumer warps (32x32 tiles,
//      acc=32 regs, ~102-reg cap) with manually double-buffered k-loop.
//      TILE_E=128, NBUF=3 ring, named barriers (128 prod / 512 cons).
// ---------------------------------------------------------------------------

#define A_PITCH 272
#define SM_B   0
#define SM_A   32768
#define A_BUF  34816                     // one fp16 plane (128*272)
#define NBUF   3
#define SM_MISC (SM_A + NBUF * A_BUF)    // 137216
#define SMEM_TOTAL (SM_MISC + 7168)      // 144384
#define NTHREADS 640
#define TILE_E 128
#define MAX_NODES 100000

__device__ u64 g_Bh[4096];               // fp16 W1 fragments, mma order
__device__ u64 g_xh[MAX_NODES * 32];     // fp16 x, 32 u64 per row

#define NB_ARRIVE(id) asm volatile("bar.arrive %0, 640;" :: "r"(id) : "memory")
#define NB_SYNC(id)   asm volatile("bar.sync %0, 640;"   :: "r"(id) : "memory")

__device__ __forceinline__ u32 pack_hf2(__half a, __half b) {
    __half2 t; t.x = a; t.y = b; return *(u32*)&t;
}
__device__ __forceinline__ u32 smem_u32(const void* p) {
    u32 a; asm("{ .reg .u64 t; cvta.to.shared.u64 t, %1; cvt.u32.u64 %0, t; }"
               : "=r"(a) : "l"(p)); return a;
}
__device__ __forceinline__ void ldmatrix_x4(u32* r, u32 saddr) {
    asm volatile("ldmatrix.sync.aligned.m8n8.x4.shared.b16 {%0,%1,%2,%3}, [%4];"
                 : "=r"(r[0]), "=r"(r[1]), "=r"(r[2]), "=r"(r[3]) : "r"(saddr));
}
__device__ __forceinline__ void mma_fp16(float* d, const u32* a, const u32* b) {
    asm volatile(
        "mma.sync.aligned.m16n8k16.row.col.f32.f16.f16.f32 "
        "{%0,%1,%2,%3}, {%4,%5,%6,%7}, {%8,%9}, {%0,%1,%2,%3};"
        : "+f"(d[0]), "+f"(d[1]), "+f"(d[2]), "+f"(d[3])
        : "r"(a[0]), "r"(a[1]), "r"(a[2]), "r"(a[3]), "r"(b[0]), "r"(b[1]));
}

// ---- prep (single launch): x -> fp16, W1 -> fp16 fragments ----
__global__ void prep_all_kernel(const float* __restrict__ W1,
                                const float* __restrict__ x, int n4) {
    int i = blockIdx.x * blockDim.x + threadIdx.x;
    if (i < n4) {
        float4 v = ((const float4*)x)[i];
        u64 p;
        ((__half2*)&p)[0] = __floats2half2_rn(v.x, v.y);
        ((__half2*)&p)[1] = __floats2half2_rn(v.z, v.w);
        g_xh[i] = p;
    }
    if (i < 4096) {
        int lane = i & 31, nt = (i >> 5) & 15, kt = i >> 9;
        int n  = nt * 8 + (lane >> 2);
        int k0 = kt * 16 + (lane & 3) * 2;
        __half h0 = __float2half(W1[(k0    ) * 128 + n]);
        __half h1 = __float2half(W1[(k0 + 1) * 128 + n]);
        __half h2 = __float2half(W1[(k0 + 8) * 128 + n]);
        __half h3 = __float2half(W1[(k0 + 9) * 128 + n]);
        int idx = ((kt * 8 + (nt >> 1)) * 32 + lane) * 2 + (nt & 1);
        g_Bh[idx] = ((u64)pack_hf2(h2, h3) << 32) | pack_hf2(h0, h1);
    }
}

__device__ __forceinline__ void conv_store(char* smem, u32 base, int row,
                                           int lane, u64 ua, u64 ub,
                                           bool valid) {
    u64 hp = 0;
    if (valid) {
        __half2 z = __float2half2_rn(0.f);
        ((__half2*)&hp)[0] =
            __hmax2(__hmul2(((__half2*)&ua)[0], ((__half2*)&ub)[0]), z);
        ((__half2*)&hp)[1] =
            __hmax2(__hmul2(((__half2*)&ua)[1], ((__half2*)&ub)[1]), z);
    }
    u32 off = (u32)row * A_PITCH + (u32)lane * 8;
    *(u64*)(smem + base + off) = hp;
}

__global__ void __launch_bounds__(NTHREADS, 1)
vgae_mma_kernel(const float* __restrict__ b1g,
                const float* __restrict__ W2,
                const float* __restrict__ b2g,
                const int*   __restrict__ ei_pos,
                const int*   __restrict__ ei_neg,
                float*       __restrict__ out,
                int E, int total, int n_tiles)
{
    extern __shared__ char smem[];
    float* sB1  = (float*)(smem + SM_MISC);          // 128 f32
    float* sW2  = (float*)(smem + SM_MISC + 512);    // 128 f32
    float* sRed = (float*)(smem + SM_MISC + 1024);   // [3][128][4] f32

    const int tid  = threadIdx.x;
    const int wid  = tid >> 5;
    const int lane = tid & 31;
    const u32 sbase = smem_u32(smem);

    {
        u64* bh = (u64*)(smem + SM_B);
        #pragma unroll 4
        for (int i = tid; i < 4096; i += NTHREADS) bh[i] = g_Bh[i];
        if (tid < 128) { sB1[tid] = b1g[tid]; sW2[tid] = W2[tid]; }
    }
    const float b2v = __ldg(b2g);
    __syncthreads();

    const bool is_prod = (wid < 4);
    const int r0 = (wid & 3) * 32;   // producer rows r0..r0+31
    const int nit = (n_tiles > (int)blockIdx.x)
                  ? (n_tiles - blockIdx.x + gridDim.x - 1) / gridDim.x : 0;

    // index load for rows RB..RB+15 of tile T (lanes 0-15 u, 16-31 v)
    #define LOAD_IDX(T, RB, IDXV) do {                                       \
        (IDXV) = 0;                                                          \
        int _e0 = (T) * TILE_E + (RB);                                       \
        const int* _ei = ei_pos; int _el = _e0;                              \
        if (_el >= E) { _ei = ei_neg; _el -= E; }                            \
        if (_e0 + (lane & 15) < total)                                       \
            (IDXV) = __ldg(_ei + _el + (lane & 15) + ((lane >= 16) ? E : 0));\
    } while (0)

    #define FETCH_ROW(IDXV, RB, J, UA, UB, VAL, TBASE) do {                  \
        (VAL) = ((TBASE) + (RB) + (J)) < total;                              \
        int _u = __shfl_sync(0xffffffffu, (IDXV), (J));                      \
        int _v = __shfl_sync(0xffffffffu, (IDXV), (J) + 16);                 \
        (UA) = __ldg(g_xh + (size_t)_u * 32 + lane);                         \
        (UB) = __ldg(g_xh + (size_t)_v * 32 + lane);                         \
    } while (0)

    // gather 32 rows (r0..r0+31) into buffer BASE
    #define GATHER32(I0, I1, BASE, TBASE) do {                               \
        _Pragma("unroll")                                                    \
        for (int g = 0; g < 2; ++g) {                                        \
            int _rb = r0 + g * 16;                                           \
            int _iv = g ? (I1) : (I0);                                       \
            _Pragma("unroll")                                                \
            for (int w = 0; w < 2; ++w) {                                    \
                u64 xa[8], xb[8]; bool vv[8];                                \
                _Pragma("unroll")                                            \
                for (int j = 0; j < 8; ++j)                                  \
                    FETCH_ROW(_iv, _rb, w * 8 + j, xa[j], xb[j], vv[j],      \
                              TBASE);                                        \
                _Pragma("unroll")                                            \
                for (int j = 0; j < 8; ++j)                                  \
                    conv_store(smem, BASE, _rb + w * 8 + j, lane, xa[j],     \
                               xb[j], vv[j]);                                \
            }                                                                \
        }                                                                    \
    } while (0)

    if (is_prod) {
        // ==================== PRODUCER WARPS (0-3) ====================
        int i = 0;
        for (int tile = blockIdx.x; tile < n_tiles; tile += gridDim.x, ++i) {
            int b = i % NBUF;
            if (i >= NBUF) {
                NB_SYNC(4 + b);                    // buffer b free + sRed ready
                if (tid < TILE_E) {
                    int e = (tile - NBUF * (int)gridDim.x) * TILE_E + tid;
                    if (e < total) {
                        const float* rp = sRed + b * 512 + tid * 4;
                        float s = rp[0] + rp[1] + rp[2] + rp[3] + b2v;
                        out[e] = 1.f / (1.f + expf(-s));
                    }
                }
            }
            int iv0, iv1;
            LOAD_IDX(tile, r0, iv0);
            LOAD_IDX(tile, r0 + 16, iv1);
            GATHER32(iv0, iv1, SM_A + (u32)b * A_BUF, tile * TILE_E);
            NB_ARRIVE(1 + b);                      // buffer b full
        }
        int j0 = (nit >= NBUF) ? nit - NBUF : 0;
        for (int j = j0; j < nit; ++j) {
            int b = j % NBUF;
            NB_SYNC(4 + b);
            if (tid < TILE_E) {
                int e = ((int)blockIdx.x + j * (int)gridDim.x) * TILE_E + tid;
                if (e < total) {
                    const float* rp = sRed + b * 512 + tid * 4;
                    float s = rp[0] + rp[1] + rp[2] + rp[3] + b2v;
                    out[e] = 1.f / (1.f + expf(-s));
                }
            }
        }
    } else {
        // ==================== CONSUMER WARPS (4-19) ====================
        const int cw = wid - 4;          // 0..15
        const int wm = cw & 3;           // 32-row m-strip
        const int wn = cw >> 2;          // 32-col n-strip
        const u32 a_lm0 = (u32)(wm * 32 + (lane & 15)) * A_PITCH
                        + (u32)(lane >> 4) * 16;

        // fragment loads for one kt into AH[2][4], BQ[4][2]
        #define LOADK(KT, AH, BQ) do {                                       \
            _Pragma("unroll")                                                \
            for (int mf = 0; mf < 2; ++mf)                                   \
                ldmatrix_x4((AH)[mf], a_lm + (u32)mf * (16 * A_PITCH)        \
                                       + (u32)(KT) * 32);                    \
            _Pragma("unroll")                                                \
            for (int np = 0; np < 2; ++np) {                                 \
                u32 boff = (u32)((((KT) * 8 + wn * 2 + np) * 32 + lane)      \
                                 * 16);                                      \
                uint4 q = *(const uint4*)(smem + SM_B + boff);               \
                (BQ)[np*2][0] = q.x; (BQ)[np*2][1] = q.y;                    \
                (BQ)[np*2+1][0] = q.z; (BQ)[np*2+1][1] = q.w;                \
            }                                                                \
        } while (0)

        int i = 0;
        for (int tile = blockIdx.x; tile < n_tiles; tile += gridDim.x, ++i) {
            int b = i % NBUF;
            NB_SYNC(1 + b);                        // buffer b full

            const u32 a_lm = sbase + SM_A + (u32)b * A_BUF + a_lm0;

            float acc[2][4][4];
            #pragma unroll
            for (int mf = 0; mf < 2; ++mf)
                #pragma unroll
                for (int nt = 0; nt < 4; ++nt)
                    #pragma unroll
                    for (int q = 0; q < 4; ++q) acc[mf][nt][q] = 0.f;

            u32 ah[2][2][4], bq[2][4][2];          // double-buffered frags
            LOADK(0, ah[0], bq[0]);
            #pragma unroll
            for (int kt = 0; kt < 8; ++kt) {
                int cb = kt & 1;
                if (kt < 7) LOADK(kt + 1, ah[cb ^ 1], bq[cb ^ 1]);
                #pragma unroll
                for (int mf = 0; mf < 2; ++mf)
                    #pragma unroll
                    for (int nt = 0; nt < 4; ++nt)
                        mma_fp16(acc[mf][nt], ah[cb][mf], bq[cb][nt]);
            }

            // epilogue: +b1, relu, dot W2, shfl-reduce -> sRed[b]
            #pragma unroll
            for (int mf = 0; mf < 2; ++mf) {
                float p0 = 0.f, p1 = 0.f;
                #pragma unroll
                for (int nt = 0; nt < 4; ++nt) {
                    int n = wn * 32 + nt * 8 + (lane & 3) * 2;
                    float bia0 = sB1[n], bia1 = sB1[n + 1];
                    float w20  = sW2[n], w21  = sW2[n + 1];
                    p0 = fmaf(fmaxf(acc[mf][nt][0] + bia0, 0.f), w20, p0);
                    p0 = fmaf(fmaxf(acc[mf][nt][1] + bia1, 0.f), w21, p0);
                    p1 = fmaf(fmaxf(acc[mf][nt][2] + bia0, 0.f), w20, p1);
                    p1 = fmaf(fmaxf(acc[mf][nt][3] + bia1, 0.f), w21, p1);
                }
                p0 += __shfl_xor_sync(0xffffffffu, p0, 1);
                p0 += __shfl_xor_sync(0xffffffffu, p0, 2);
                p1 += __shfl_xor_sync(0xffffffffu, p1, 1);
                p1 += __shfl_xor_sync(0xffffffffu, p1, 2);
                if ((lane & 3) == 0) {
                    int rr = wm * 32 + mf * 16 + (lane >> 2);
                    float* rb = sRed + b * 512;
                    rb[rr * 4 + wn] = p0;
                    rb[(rr + 8) * 4 + wn] = p1;
                }
            }
            NB_ARRIVE(4 + b);                      // buffer b free + sRed ready
        }
        #undef LOADK
    }
    #undef LOAD_IDX
    #undef FETCH_ROW
    #undef GATHER32
}

// ---------------------------------------------------------------------------
extern "C" void kernel_launch(void* const* d_in, const int* in_sizes, int n_in,
                              void* d_out, int out_size)
{
    const float* x  = (const float*)d_in[0];
    const float* W1 = (const float*)d_in[1];
    const float* b1 = (const float*)d_in[2];
    const float* W2 = (const float*)d_in[3];
    const float* b2 = (const float*)d_in[4];
    const int* eip  = (const int*)d_in[5];
    const int* ein  = (const int*)d_in[6];
    float* out = (float*)d_out;

    int E       = in_sizes[5] / 2;
    int total   = out_size;
    int n_tiles = (total + TILE_E - 1) / TILE_E;

    int n4 = in_sizes[0] / 4;
    if (n4 > MAX_NODES * 32) n4 = MAX_NODES * 32;

    prep_all_kernel<<<(n4 + 255) / 256, 256>>>(W1, x, n4);

    cudaFuncSetAttribute(vgae_mma_kernel,
                         cudaFuncAttributeMaxDynamicSharedMemorySize, SMEM_TOTAL);
    int grid = 148;
    if (grid > n_tiles) grid = n_tiles;
    vgae_mma_kernel<<<grid, NTHREADS, SMEM_TOTAL>>>(b1, W2, b2, eip, ein,
                                                    out, E, total, n_tiles);
}

// round 15
// speedup vs baseline: 2.0266x; 1.3076x over previous
#include <cuda_runtime.h>
#include <cuda_fp16.h>
#include <math.h>
#include <stdint.h>

typedef unsigned int u32;
typedef unsigned long long u64;

// ---------------------------------------------------------------------------
// vgae_decoder, warp-specialized single-pass fp16 mma (R12 geometry):
//   D = fp16(xu)*fp16(xv) relu'd @ fp16(W1)   (fp32 accumulate)
// R15: merged prep (1 launch), packed (b1,W2) float2 epilogue loads, NBUF=4.
// 148 persistent blocks x 512 threads, 128-edge tiles.
//   warps 0-7  : producers (gather fp16 x, HMUL2/HMAX2, STS; deferred STG)
//   warps 8-15 : consumers (MMA 32x64 warp tile, partial epilogue -> sRed)
// ---------------------------------------------------------------------------

#define A_PITCH 272
#define SM_B   0
#define SM_A   32768
#define A_BUF  34816                     // one fp16 plane (128*272)
#define NBUF   4
#define SM_MISC (SM_A + NBUF * A_BUF)    // 172032
#define SMEM_TOTAL (SM_MISC + 6144)      // 178176
#define NTHREADS 512
#define TILE_E 128
#define MAX_NODES 100000

__device__ u64 g_Bh[4096];               // fp16 W1 fragments, mma order
__device__ u64 g_xh[MAX_NODES * 32];     // fp16 x, 32 u64 per row

#define NB_ARRIVE(id) asm volatile("bar.arrive %0, 512;" :: "r"(id) : "memory")
#define NB_SYNC(id)   asm volatile("bar.sync %0, 512;"   :: "r"(id) : "memory")

__device__ __forceinline__ u32 pack_hf2(__half a, __half b) {
    __half2 t; t.x = a; t.y = b; return *(u32*)&t;
}
__device__ __forceinline__ u32 smem_u32(const void* p) {
    u32 a; asm("{ .reg .u64 t; cvta.to.shared.u64 t, %1; cvt.u32.u64 %0, t; }"
               : "=r"(a) : "l"(p)); return a;
}
__device__ __forceinline__ void ldmatrix_x4(u32* r, u32 saddr) {
    asm volatile("ldmatrix.sync.aligned.m8n8.x4.shared.b16 {%0,%1,%2,%3}, [%4];"
                 : "=r"(r[0]), "=r"(r[1]), "=r"(r[2]), "=r"(r[3]) : "r"(saddr));
}
__device__ __forceinline__ void mma_fp16(float* d, const u32* a, const u32* b) {
    asm volatile(
        "mma.sync.aligned.m16n8k16.row.col.f32.f16.f16.f32 "
        "{%0,%1,%2,%3}, {%4,%5,%6,%7}, {%8,%9}, {%0,%1,%2,%3};"
        : "+f"(d[0]), "+f"(d[1]), "+f"(d[2]), "+f"(d[3])
        : "r"(a[0]), "r"(a[1]), "r"(a[2]), "r"(a[3]), "r"(b[0]), "r"(b[1]));
}

// ---- prep (single launch): x -> fp16, W1 -> fp16 fragments ----
__global__ void prep_all_kernel(const float* __restrict__ W1,
                                const float* __restrict__ x, int n4) {
    int i = blockIdx.x * blockDim.x + threadIdx.x;
    if (i < n4) {
        float4 v = ((const float4*)x)[i];
        u64 p;
        ((__half2*)&p)[0] = __floats2half2_rn(v.x, v.y);
        ((__half2*)&p)[1] = __floats2half2_rn(v.z, v.w);
        g_xh[i] = p;
    }
    if (i < 4096) {
        int lane = i & 31, nt = (i >> 5) & 15, kt = i >> 9;
        int n  = nt * 8 + (lane >> 2);
        int k0 = kt * 16 + (lane & 3) * 2;
        __half h0 = __float2half(W1[(k0    ) * 128 + n]);
        __half h1 = __float2half(W1[(k0 + 1) * 128 + n]);
        __half h2 = __float2half(W1[(k0 + 8) * 128 + n]);
        __half h3 = __float2half(W1[(k0 + 9) * 128 + n]);
        int idx = ((kt * 8 + (nt >> 1)) * 32 + lane) * 2 + (nt & 1);
        g_Bh[idx] = ((u64)pack_hf2(h2, h3) << 32) | pack_hf2(h0, h1);
    }
}

__device__ __forceinline__ void conv_store(char* smem, u32 base, int row,
                                           int lane, u64 ua, u64 ub,
                                           bool valid) {
    u64 hp = 0;
    if (valid) {
        __half2 z = __float2half2_rn(0.f);
        ((__half2*)&hp)[0] =
            __hmax2(__hmul2(((__half2*)&ua)[0], ((__half2*)&ub)[0]), z);
        ((__half2*)&hp)[1] =
            __hmax2(__hmul2(((__half2*)&ua)[1], ((__half2*)&ub)[1]), z);
    }
    u32 off = (u32)row * A_PITCH + (u32)lane * 8;
    *(u64*)(smem + base + off) = hp;
}

__global__ void __launch_bounds__(NTHREADS, 1)
vgae_mma_kernel(const float* __restrict__ b1g,
                const float* __restrict__ W2,
                const float* __restrict__ b2g,
                const int*   __restrict__ ei_pos,
                const int*   __restrict__ ei_neg,
                float*       __restrict__ out,
                int E, int total, int n_tiles)
{
    extern __shared__ char smem[];
    float2* sBW = (float2*)(smem + SM_MISC);         // 128 x (b1, W2)
    float*  sRed = (float*)(smem + SM_MISC + 1024);  // [4][128][2] f32

    const int tid  = threadIdx.x;
    const int wid  = tid >> 5;
    const int lane = tid & 31;
    const u32 sbase = smem_u32(smem);

    {
        u64* bh = (u64*)(smem + SM_B);
        #pragma unroll 4
        for (int i = tid; i < 4096; i += NTHREADS) bh[i] = g_Bh[i];
        if (tid < 128) sBW[tid] = make_float2(b1g[tid], W2[tid]);
    }
    const float b2v = __ldg(b2g);
    __syncthreads();

    const bool is_prod = (wid < 8);
    const int r0 = (wid & 7) * 16;
    const int nit = (n_tiles > (int)blockIdx.x)
                  ? (n_tiles - blockIdx.x + gridDim.x - 1) / gridDim.x : 0;

    #define LOAD_IDX(T, IDXV) do {                                           \
        (IDXV) = 0;                                                          \
        int _e0 = (T) * TILE_E + r0;                                         \
        const int* _ei = ei_pos; int _el = _e0;                              \
        if (_el >= E) { _ei = ei_neg; _el -= E; }                            \
        if (_e0 + (lane & 15) < total)                                       \
            (IDXV) = __ldg(_ei + _el + (lane & 15) + ((lane >= 16) ? E : 0));\
    } while (0)

    #define FETCH_ROW(IDXV, J, UA, UB, VAL, TBASE) do {                      \
        (VAL) = ((TBASE) + r0 + (J)) < total;                                \
        int _u = __shfl_sync(0xffffffffu, (IDXV), (J));                      \
        int _v = __shfl_sync(0xffffffffu, (IDXV), (J) + 16);                 \
        (UA) = __ldg(g_xh + (size_t)_u * 32 + lane);                         \
        (UB) = __ldg(g_xh + (size_t)_v * 32 + lane);                         \
    } while (0)

    #define GATHER16(IDXV, BASE, TBASE) do {                                 \
        _Pragma("unroll")                                                    \
        for (int w = 0; w < 2; ++w) {                                        \
            u64 xa[8], xb[8]; bool vv[8];                                    \
            _Pragma("unroll")                                                \
            for (int j = 0; j < 8; ++j)                                      \
                FETCH_ROW(IDXV, w * 8 + j, xa[j], xb[j], vv[j], TBASE);      \
            _Pragma("unroll")                                                \
            for (int j = 0; j < 8; ++j)                                      \
                conv_store(smem, BASE, r0 + w * 8 + j, lane, xa[j], xb[j],   \
                           vv[j]);                                           \
        }                                                                    \
    } while (0)

    if (is_prod) {
        // ==================== PRODUCER WARPS (0-7) ====================
        int i = 0;
        for (int tile = blockIdx.x; tile < n_tiles; tile += gridDim.x, ++i) {
            int b = i % NBUF;
            if (i >= NBUF) {
                NB_SYNC(5 + b);                    // buffer b free + sRed ready
                if (tid < TILE_E) {
                    int e = (tile - NBUF * (int)gridDim.x) * TILE_E + tid;
                    if (e < total) {
                        const float* rp = sRed + b * 256 + tid * 2;
                        float s = rp[0] + rp[1] + b2v;
                        out[e] = 1.f / (1.f + expf(-s));
                    }
                }
            }
            int idxv; LOAD_IDX(tile, idxv);
            GATHER16(idxv, SM_A + (u32)b * A_BUF, tile * TILE_E);
            NB_ARRIVE(1 + b);                      // buffer b full
        }
        int j0 = (nit >= NBUF) ? nit - NBUF : 0;
        for (int j = j0; j < nit; ++j) {
            int b = j % NBUF;
            NB_SYNC(5 + b);
            if (tid < TILE_E) {
                int e = ((int)blockIdx.x + j * (int)gridDim.x) * TILE_E + tid;
                if (e < total) {
                    const float* rp = sRed + b * 256 + tid * 2;
                    float s = rp[0] + rp[1] + b2v;
                    out[e] = 1.f / (1.f + expf(-s));
                }
            }
        }
    } else {
        // ==================== CONSUMER WARPS (8-15) ====================
        const int cw = wid - 8;
        const int wm = cw & 3;           // 32-row m-strip
        const int wn = cw >> 2;          // 64-col n-strip
        const u32 a_lm0 = (u32)(wm * 32 + (lane & 15)) * A_PITCH
                        + (u32)(lane >> 4) * 16;

        int i = 0;
        for (int tile = blockIdx.x; tile < n_tiles; tile += gridDim.x, ++i) {
            int b = i % NBUF;
            NB_SYNC(1 + b);                        // buffer b full

            const u32 a_lm = sbase + SM_A + (u32)b * A_BUF + a_lm0;
            float acc[2][8][4];
            #pragma unroll
            for (int mf = 0; mf < 2; ++mf)
                #pragma unroll
                for (int nt = 0; nt < 8; ++nt)
                    #pragma unroll
                    for (int c = 0; c < 4; ++c) acc[mf][nt][c] = 0.f;

            #pragma unroll
            for (int kt = 0; kt < 8; ++kt) {
                u32 ah[2][4];
                #pragma unroll
                for (int mf = 0; mf < 2; ++mf)
                    ldmatrix_x4(ah[mf],
                                a_lm + (u32)mf * (16 * A_PITCH) + (u32)kt * 32);
                u32 bq[8][2];
                #pragma unroll
                for (int np = 0; np < 4; ++np) {
                    u32 boff = (u32)(((kt * 8 + wn * 4 + np) * 32 + lane)
                                     * 16);
                    uint4 q = *(const uint4*)(smem + SM_B + boff);
                    bq[np*2][0] = q.x; bq[np*2][1] = q.y;
                    bq[np*2+1][0] = q.z; bq[np*2+1][1] = q.w;
                }
                #pragma unroll
                for (int mf = 0; mf < 2; ++mf)
                    #pragma unroll
                    for (int nt = 0; nt < 8; ++nt)
                        mma_fp16(acc[mf][nt], ah[mf], bq[nt]);
            }

            // partial epilogue: +b1, relu, dot W2 (packed float2), reduce
            #pragma unroll
            for (int mf = 0; mf < 2; ++mf) {
                float p0 = 0.f, p1 = 0.f;
                #pragma unroll
                for (int nt = 0; nt < 8; ++nt) {
                    int n = wn * 64 + nt * 8 + (lane & 3) * 2;
                    float2 bw0 = sBW[n], bw1 = sBW[n + 1];
                    p0 = fmaf(fmaxf(acc[mf][nt][0] + bw0.x, 0.f), bw0.y, p0);
                    p0 = fmaf(fmaxf(acc[mf][nt][1] + bw1.x, 0.f), bw1.y, p0);
                    p1 = fmaf(fmaxf(acc[mf][nt][2] + bw0.x, 0.f), bw0.y, p1);
                    p1 = fmaf(fmaxf(acc[mf][nt][3] + bw1.x, 0.f), bw1.y, p1);
                }
                p0 += __shfl_xor_sync(0xffffffffu, p0, 1);
                p0 += __shfl_xor_sync(0xffffffffu, p0, 2);
                p1 += __shfl_xor_sync(0xffffffffu, p1, 1);
                p1 += __shfl_xor_sync(0xffffffffu, p1, 2);
                if ((lane & 3) == 0) {
                    int rr = wm * 32 + mf * 16 + (lane >> 2);
                    float* rb = sRed + b * 256;
                    rb[rr * 2 + wn] = p0;
                    rb[(rr + 8) * 2 + wn] = p1;
                }
            }
            NB_ARRIVE(5 + b);                      // buffer b free + sRed ready
        }
    }
    #undef LOAD_IDX
    #undef FETCH_ROW
    #undef GATHER16
}

// ---------------------------------------------------------------------------
extern "C" void kernel_launch(void* const* d_in, const int* in_sizes, int n_in,
                              void* d_out, int out_size)
{
    const float* x  = (const float*)d_in[0];
    const float* W1 = (const float*)d_in[1];
    const float* b1 = (const float*)d_in[2];
    const float* W2 = (const float*)d_in[3];
    const float* b2 = (const float*)d_in[4];
    const int* eip  = (const int*)d_in[5];
    const int* ein  = (const int*)d_in[6];
    float* out = (float*)d_out;

    int E       = in_sizes[5] / 2;
    int total   = out_size;
    int n_tiles = (total + TILE_E - 1) / TILE_E;

    int n4 = in_sizes[0] / 4;
    if (n4 > MAX_NODES * 32) n4 = MAX_NODES * 32;

    prep_all_kernel<<<(n4 + 255) / 256, 256>>>(W1, x, n4);

    cudaFuncSetAttribute(vgae_mma_kernel,
                         cudaFuncAttributeMaxDynamicSharedMemorySize, SMEM_TOTAL);
    int grid = 148;
    if (grid > n_tiles) grid = n_tiles;
    vgae_mma_kernel<<<grid, NTHREADS, SMEM_TOTAL>>>(b1, W2, b2, eip, ein,
                                                    out, E, total, n_tiles);
}